// round 13
// baseline (speedup 1.0000x reference)
#include <cuda_runtime.h>
#include <cuda_bf16.h>
#include <math.h>
#include <stdint.h>

// Problem constants
#define B_   128
#define N_   197
#define C_   768
#define H_   12
#define HD_  64
#define NC3_ 2304
#define M_   (B_ * N_)     // 25216
#define NREL (38809)
#define SCALE 0.125f

// ---------------------------------------------------------------------------
// Scratch
// ---------------------------------------------------------------------------
__device__ float g_Q[B_ * H_ * N_ * HD_];
__device__ float g_K[B_ * H_ * N_ * HD_];
__device__ float g_V[B_ * H_ * N_ * HD_];
__device__ float g_O[M_ * C_];              // tf32-rounded by attn epilogue
__device__ float g_RB[H_ * NREL];
__device__ float g_xr[M_ * C_];             // tf32-rounded x
__device__ float g_wqkv[NC3_ * C_];         // tf32-rounded qkv_w
__device__ float g_wproj[C_ * C_];          // tf32-rounded proj_w

// ---------------------------------------------------------------------------
// helpers
// ---------------------------------------------------------------------------
__device__ __forceinline__ uint32_t f2tf(float x) {
    uint32_t u;
    asm("cvt.rna.tf32.f32 %0, %1;" : "=r"(u) : "f"(x));
    return u;
}
__device__ __forceinline__ void mma_tf32(float c[4], const uint32_t a[4],
                                         uint32_t b0, uint32_t b1) {
    asm volatile(
        "mma.sync.aligned.m16n8k8.row.col.f32.tf32.tf32.f32 "
        "{%0,%1,%2,%3}, {%4,%5,%6,%7}, {%8,%9}, {%0,%1,%2,%3};"
        : "+f"(c[0]), "+f"(c[1]), "+f"(c[2]), "+f"(c[3])
        : "r"(a[0]), "r"(a[1]), "r"(a[2]), "r"(a[3]), "r"(b0), "r"(b1));
}
__device__ __forceinline__ uint32_t smem_u32(const void* p) {
    return (uint32_t)__cvta_generic_to_shared(p);
}
__device__ __forceinline__ void cpasync16(uint32_t dst, const void* src) {
    asm volatile("cp.async.cg.shared.global [%0], [%1], 16;" :: "r"(dst), "l"(src));
}
__device__ __forceinline__ void cp_commit() {
    asm volatile("cp.async.commit_group;");
}
template <int Nn> __device__ __forceinline__ void cp_wait() {
    asm volatile("cp.async.wait_group %0;" :: "n"(Nn));
}
__device__ __forceinline__ void ldsm4(uint32_t& r0, uint32_t& r1,
                                      uint32_t& r2, uint32_t& r3, uint32_t a) {
    asm volatile("ldmatrix.sync.aligned.m8n8.x4.shared.b16 {%0,%1,%2,%3}, [%4];"
                 : "=r"(r0), "=r"(r1), "=r"(r2), "=r"(r3) : "r"(a));
}
__device__ __forceinline__ void ldsm2(uint32_t& r0, uint32_t& r1, uint32_t a) {
    asm volatile("ldmatrix.sync.aligned.m8n8.x2.shared.b16 {%0,%1}, [%2];"
                 : "=r"(r0), "=r"(r1) : "r"(a));
}

// FMA-pipe exp: exp(x) = 2^(x*log2e), |x| clamped >= -80 upstream.
__device__ __forceinline__ float fexp(float x) {
    float y = x * 1.44269504f;
    float r = rintf(y);
    float f = y - r;
    float p = 1.33336e-3f;
    p = fmaf(p, f, 9.61813e-3f);
    p = fmaf(p, f, 5.55041e-2f);
    p = fmaf(p, f, 2.40226507e-1f);
    p = fmaf(p, f, 6.93147182e-1f);
    p = fmaf(p, f, 1.0f);
    int i = (int)r;
    return p * __int_as_float((127 + i) << 23);
}

// ---------------------------------------------------------------------------
// tf32 pre-round (RNA)
// ---------------------------------------------------------------------------
__global__ void round_kernel(const float* __restrict__ s, float* __restrict__ d, int n4) {
    int i = blockIdx.x * 256 + threadIdx.x;
    if (i < n4) {
        float4 v = ((const float4*)s)[i];
        v.x = __uint_as_float(f2tf(v.x));
        v.y = __uint_as_float(f2tf(v.y));
        v.z = __uint_as_float(f2tf(v.z));
        v.w = __uint_as_float(f2tf(v.w));
        ((float4*)d)[i] = v;
    }
}

// ---------------------------------------------------------------------------
// relbias gather
// ---------------------------------------------------------------------------
__global__ void relbias_kernel(const float* __restrict__ table,
                               const int* __restrict__ idx) {
    int i = blockIdx.x * 256 + threadIdx.x;
    if (i < H_ * NREL) {
        int h = i / NREL;
        int r = i - h * NREL;
        g_RB[i] = table[idx[r] * H_ + h];
    }
}

// ---------------------------------------------------------------------------
// Wide-tile TF32 GEMM core: CTA 128x256, 8 warps (2M x 4N), warp tile 64x64.
// BK=32, 3-stage cp.async, xor swizzle, ldmatrix. Inputs pre-rounded tf32.
// ---------------------------------------------------------------------------
#define TCN 256
#define NSTG 3
#define STGB 49152                  // stage: A 16KB + B 32KB
#define GEMM_SMEM (1024 + NSTG * STGB)
#define GNT (C_ / 32)               // 24 k-tiles

__device__ __forceinline__ void tf32_core_w64(
    const float* __restrict__ A, const float* __restrict__ W,
    float acc[4][8][4])
{
    extern __shared__ uint32_t smp[];
    const uint32_t base = (smem_u32(smp) + 1023) & ~1023u;

    const int tid = threadIdx.x;
    const int lane = tid & 31;
    const int warp = tid >> 5;
    const int wm = warp & 1, wn = warp >> 1;
    const int brow = blockIdx.y * 128;
    const int bcol = blockIdx.x * TCN;

    // fill: every thread one B row; threads <128 also one A row
    const float* gB = W + (size_t)(bcol + tid) * C_;
    const uint32_t soB = 16384u + (uint32_t)tid * 128u;
    const bool hasA = tid < 128;
    const float* gA = A + (size_t)(brow + (tid & 127)) * C_;
    const uint32_t soA = (uint32_t)(tid & 127) * 128u;
    const int sw = tid & 7;

    auto issue = [&](int t) {
        uint32_t stb = base + (uint32_t)(t % NSTG) * STGB;
        const float* p = gB + t * 32;
        #pragma unroll
        for (int j = 0; j < 8; ++j)
            cpasync16(stb + soB + (uint32_t)((j ^ sw) << 4), p + j * 4);
        if (hasA) {
            const float* q = gA + t * 32;
            #pragma unroll
            for (int j = 0; j < 8; ++j)
                cpasync16(stb + soA + (uint32_t)((j ^ sw) << 4), q + j * 4);
        }
        cp_commit();
    };

    issue(0);
    issue(1);

    const int ti = lane >> 3, rsub = lane & 7;
    uint32_t aB[4]; int rwA[4];
    #pragma unroll
    for (int mi = 0; mi < 4; ++mi) {
        int rr = wm * 64 + mi * 16 + ((ti & 1) << 3) + rsub;
        rwA[mi] = rr & 7;
        aB[mi] = base + (uint32_t)rr * 128u;
    }
    const int kgbA = ti >> 1;
    uint32_t bB[4]; int rwB[4];
    #pragma unroll
    for (int p = 0; p < 4; ++p) {
        int rr = wn * 64 + p * 16 + ((ti >> 1) << 3) + rsub;
        rwB[p] = rr & 7;
        bB[p] = base + 16384u + (uint32_t)rr * 128u;
    }
    const int kgbB = ti & 1;

    for (int t = 0; t < GNT; ++t) {
        if (t + 1 < GNT) cp_wait<1>(); else cp_wait<0>();
        __syncthreads();
        if (t + 2 < GNT) issue(t + 2);
        const uint32_t so = (uint32_t)(t % NSTG) * STGB;
        #pragma unroll
        for (int kk = 0; kk < 4; ++kk) {
            uint32_t af[4][4];
            #pragma unroll
            for (int mi = 0; mi < 4; ++mi) {
                uint32_t addr = aB[mi] + so +
                    (uint32_t)((((2 * kk + kgbA) ^ rwA[mi]) & 7) << 4);
                ldsm4(af[mi][0], af[mi][1], af[mi][2], af[mi][3], addr);
            }
            #pragma unroll
            for (int p = 0; p < 4; ++p) {
                uint32_t b0a, b1a, b0b, b1b;
                uint32_t addr = bB[p] + so +
                    (uint32_t)((((2 * kk + kgbB) ^ rwB[p]) & 7) << 4);
                ldsm4(b0a, b1a, b0b, b1b, addr);
                #pragma unroll
                for (int mi = 0; mi < 4; ++mi) {
                    mma_tf32(acc[mi][2 * p],     af[mi], b0a, b1a);
                    mma_tf32(acc[mi][2 * p + 1], af[mi], b0b, b1b);
                }
            }
        }
    }
}

// ---------------------------------------------------------------------------
// QKV GEMM + scatter epilogue
// ---------------------------------------------------------------------------
__global__ __launch_bounds__(256, 1)
void qkv_kernel(const float* __restrict__ q_bias, const float* __restrict__ v_bias)
{
    float acc[4][8][4];
    #pragma unroll
    for (int i = 0; i < 4; ++i)
        #pragma unroll
        for (int j = 0; j < 8; ++j)
            #pragma unroll
            for (int k = 0; k < 4; ++k) acc[i][j][k] = 0.f;

    tf32_core_w64(g_xr, g_wqkv, acc);

    const int lane = threadIdx.x & 31;
    const int warp = threadIdx.x >> 5;
    const int wm = warp & 1, wn = warp >> 1;
    const int brow = blockIdx.y * 128;
    const int bcol = blockIdx.x * TCN;

    const int which = bcol / C_;            // 256-blocks never straddle q/k/v
    const int ccbase = bcol % C_;

    #pragma unroll
    for (int mi = 0; mi < 4; ++mi) {
        #pragma unroll
        for (int rh = 0; rh < 2; ++rh) {
            int row = brow + wm * 64 + mi * 16 + (lane >> 2) + rh * 8;
            int b = row / N_;
            int n = row - b * N_;
            #pragma unroll
            for (int ni = 0; ni < 8; ++ni) {
                #pragma unroll
                for (int cj = 0; cj < 2; ++cj) {
                    int cc = ccbase + wn * 64 + ni * 8 + (lane & 3) * 2 + cj;
                    int h = cc >> 6;
                    int d = cc & 63;
                    size_t dst = (((size_t)(b * H_ + h) * N_) + n) * HD_ + d;
                    float v = acc[mi][ni][rh * 2 + cj];
                    if (which == 0)      g_Q[dst] = (v + q_bias[cc]) * SCALE;
                    else if (which == 1) g_K[dst] = v;
                    else                 g_V[dst] = v + v_bias[cc];
                }
            }
        }
    }
}

// ---------------------------------------------------------------------------
// Proj GEMM + bias epilogue
// ---------------------------------------------------------------------------
__global__ __launch_bounds__(256, 1)
void proj_kernel(const float* __restrict__ proj_b, float* __restrict__ out)
{
    float acc[4][8][4];
    #pragma unroll
    for (int i = 0; i < 4; ++i)
        #pragma unroll
        for (int j = 0; j < 8; ++j)
            #pragma unroll
            for (int k = 0; k < 4; ++k) acc[i][j][k] = 0.f;

    tf32_core_w64(g_O, g_wproj, acc);

    const int lane = threadIdx.x & 31;
    const int warp = threadIdx.x >> 5;
    const int wm = warp & 1, wn = warp >> 1;
    const int brow = blockIdx.y * 128;
    const int bcol = blockIdx.x * TCN;

    #pragma unroll
    for (int mi = 0; mi < 4; ++mi) {
        #pragma unroll
        for (int rh = 0; rh < 2; ++rh) {
            int row = brow + wm * 64 + mi * 16 + (lane >> 2) + rh * 8;
            #pragma unroll
            for (int ni = 0; ni < 8; ++ni) {
                #pragma unroll
                for (int cj = 0; cj < 2; ++cj) {
                    int col = bcol + wn * 64 + ni * 8 + (lane & 3) * 2 + cj;
                    out[(size_t)row * C_ + col] = acc[mi][ni][rh * 2 + cj] + proj_b[col];
                }
            }
        }
    }
}

// ---------------------------------------------------------------------------
// Tensor-core fused attention (ldmatrix + mma.sync; FMA-pipe exp)
// ---------------------------------------------------------------------------
#define AP 68
#define SP 212
#define ATTN_SMEM_WORDS (208 * AP + 64 * SP + 64 * SP + 64 * AP)

__global__ __launch_bounds__(256)
void attn_kernel()
{
    extern __shared__ uint32_t smu[];
    uint32_t* Ks = smu;
    uint32_t* Vt = Ks + 208 * AP;
    float*    S  = (float*)(Vt + 64 * SP);
    uint32_t* Qs = (uint32_t*)S + 64 * SP;

    const uint32_t KsB = smem_u32(Ks);
    const uint32_t VtB = smem_u32(Vt);
    const uint32_t SB  = smem_u32(S);
    const uint32_t QsB = smem_u32(Qs);

    const int bh = blockIdx.x;
    const int h = bh % H_;
    const int b = bh / H_;
    const int tid = threadIdx.x;
    const int lane = tid & 31;
    const int warp = tid >> 5;
    const int wm = warp & 3;
    const int wn = warp >> 2;

    const float* Kg = g_K + (size_t)bh * N_ * HD_;
    const float* Vg = g_V + (size_t)bh * N_ * HD_;

    for (int i = tid; i < N_ * HD_; i += 256) {
        int m = i >> 6, d = i & 63;
        Ks[m * AP + d] = f2tf(Kg[i]);
        Vt[d * SP + m] = f2tf(Vg[i]);
    }
    for (int i = tid; i < (208 - N_) * HD_; i += 256) {
        int m = N_ + (i >> 6), d = i & 63;
        Ks[m * AP + d] = 0;
    }
    for (int i = tid; i < HD_ * (SP - N_); i += 256) {
        int d = i / (SP - N_), m = N_ + i % (SP - N_);
        Vt[d * SP + m] = 0;
    }
    __syncthreads();

    const float* rb = g_RB + (size_t)h * NREL;
    const int r0 = wm * 16 + (lane >> 2);
    const int ti = lane >> 3, rsub = lane & 7;

    const uint32_t qA = QsB + (uint32_t)((wm * 16 + ((ti & 1) << 3) + rsub) * AP) * 4
                            + (uint32_t)(ti >> 1) * 16;
    uint32_t kB[6];
    #pragma unroll
    for (int q = 0; q < 6; ++q)
        kB[q] = KsB + (uint32_t)(((4 * q + 2 * (ti >> 1) + wn) * 8 + rsub) * AP) * 4
                    + (uint32_t)(ti & 1) * 16;
    const uint32_t kB12 = KsB + (uint32_t)(((24 + wn) * 8 + (lane & 7)) * AP) * 4
                              + (uint32_t)((lane >> 3) & 1) * 16;
    const uint32_t sA = SB + (uint32_t)((wm * 16 + ((ti & 1) << 3) + rsub) * SP) * 4
                           + (uint32_t)(ti >> 1) * 16;
    uint32_t vB[2];
    #pragma unroll
    for (int q = 0; q < 2; ++q)
        vB[q] = VtB + (uint32_t)((wn * 32 + q * 16 + ((ti >> 1) << 3) + rsub) * SP) * 4
                    + (uint32_t)(ti & 1) * 16;

    for (int qb = 0; qb < 4; ++qb) {
        {
            int r = tid >> 2;
            int c0 = (tid & 3) * 16;
            int qg = qb * 64 + r;
            uint32_t* dst = &Qs[r * AP + c0];
            if (qg < N_) {
                const float* qp = g_Q + ((size_t)bh * N_ + qg) * HD_ + c0;
                #pragma unroll
                for (int j = 0; j < 16; j += 4) {
                    float4 v = *(const float4*)(qp + j);
                    dst[j]     = f2tf(v.x);
                    dst[j + 1] = f2tf(v.y);
                    dst[j + 2] = f2tf(v.z);
                    dst[j + 3] = f2tf(v.w);
                }
            } else {
                #pragma unroll
                for (int j = 0; j < 16; ++j) dst[j] = 0;
            }
        }
        __syncthreads();

        {
            float acc[13][4];
            #pragma unroll
            for (int t = 0; t < 13; ++t)
                #pragma unroll
                for (int k = 0; k < 4; ++k) acc[t][k] = 0.f;

            #pragma unroll
            for (int kk = 0; kk < 8; ++kk) {
                uint32_t af[4];
                ldsm4(af[0], af[1], af[2], af[3], qA + kk * 32);
                #pragma unroll
                for (int q = 0; q < 6; ++q) {
                    uint32_t b0a, b1a, b0b, b1b;
                    ldsm4(b0a, b1a, b0b, b1b, kB[q] + kk * 32);
                    mma_tf32(acc[2 * q],     af, b0a, b1a);
                    mma_tf32(acc[2 * q + 1], af, b0b, b1b);
                }
                uint32_t c0, c1;
                ldsm2(c0, c1, kB12 + kk * 32);
                mma_tf32(acc[12], af, c0, c1);
            }
            #pragma unroll
            for (int t = 0; t < 13; ++t) {
                int n0 = (t * 2 + wn) * 8 + (lane & 3) * 2;
                S[(r0)     * SP + n0]     = acc[t][0];
                S[(r0)     * SP + n0 + 1] = acc[t][1];
                S[(r0 + 8) * SP + n0]     = acc[t][2];
                S[(r0 + 8) * SP + n0 + 1] = acc[t][3];
            }
        }
        __syncthreads();

        for (int ri = 0; ri < 8; ++ri) {
            int r = warp * 8 + ri;
            int qg = qb * 64 + r;
            if (lane < SP - N_) S[r * SP + N_ + lane] = 0.0f;
            if (qg >= N_) continue;
            const float* rbr = rb + (size_t)qg * N_;
            float s[7];
            float mx = -3.4e38f;
            #pragma unroll
            for (int j = 0; j < 7; ++j) {
                int m = lane + 32 * j;
                s[j] = (m < N_) ? S[r * SP + m] + rbr[m] : -3.4e38f;
                mx = fmaxf(mx, s[j]);
            }
            #pragma unroll
            for (int o = 16; o > 0; o >>= 1)
                mx = fmaxf(mx, __shfl_xor_sync(0xffffffffu, mx, o));
            float sum = 0.f;
            #pragma unroll
            for (int j = 0; j < 7; ++j) {
                s[j] = fexp(fmaxf(s[j] - mx, -80.f));   // FMA-pipe exp
                sum += s[j];
            }
            #pragma unroll
            for (int o = 16; o > 0; o >>= 1)
                sum += __shfl_xor_sync(0xffffffffu, sum, o);
            float inv = 1.0f / sum;
            uint32_t* Su = (uint32_t*)S;
            #pragma unroll
            for (int j = 0; j < 7; ++j) {
                int m = lane + 32 * j;
                if (m < N_) Su[r * SP + m] = f2tf(s[j] * inv);
            }
        }
        __syncthreads();

        {
            float acc2[4][4];
            #pragma unroll
            for (int t = 0; t < 4; ++t)
                #pragma unroll
                for (int k = 0; k < 4; ++k) acc2[t][k] = 0.f;

            #pragma unroll 2
            for (int kk = 0; kk < 26; ++kk) {
                uint32_t af[4];
                ldsm4(af[0], af[1], af[2], af[3], sA + kk * 32);
                #pragma unroll
                for (int q = 0; q < 2; ++q) {
                    uint32_t b0a, b1a, b0b, b1b;
                    ldsm4(b0a, b1a, b0b, b1b, vB[q] + kk * 32);
                    mma_tf32(acc2[2 * q],     af, b0a, b1a);
                    mma_tf32(acc2[2 * q + 1], af, b0b, b1b);
                }
            }
            #pragma unroll
            for (int rr = 0; rr < 2; ++rr) {
                int qg = qb * 64 + r0 + rr * 8;
                if (qg < N_) {
                    float* op = g_O + ((size_t)(b * N_ + qg)) * C_ + h * HD_ + wn * 32;
                    #pragma unroll
                    for (int t = 0; t < 4; ++t) {
                        op[t * 8 + (lane & 3) * 2] =
                            __uint_as_float(f2tf(acc2[t][rr * 2]));
                        op[t * 8 + (lane & 3) * 2 + 1] =
                            __uint_as_float(f2tf(acc2[t][rr * 2 + 1]));
                    }
                }
            }
        }
        __syncthreads();
    }
}

// ---------------------------------------------------------------------------
// Launch
// ---------------------------------------------------------------------------
extern "C" void kernel_launch(void* const* d_in, const int* in_sizes, int n_in,
                              void* d_out, int out_size)
{
    (void)in_sizes; (void)n_in; (void)out_size;
    const float* x      = (const float*)d_in[0];
    const float* qkv_w  = (const float*)d_in[1];
    const float* q_bias = (const float*)d_in[2];
    const float* v_bias = (const float*)d_in[3];
    const float* table  = (const float*)d_in[4];
    const float* proj_w = (const float*)d_in[5];
    const float* proj_b = (const float*)d_in[6];
    const int*   ridx   = (const int*)d_in[7];
    float* out = (float*)d_out;

    const int attn_smem = ATTN_SMEM_WORDS * (int)sizeof(uint32_t);
    cudaFuncSetAttribute(attn_kernel,
                         cudaFuncAttributeMaxDynamicSharedMemorySize, attn_smem);
    cudaFuncSetAttribute(qkv_kernel,
                         cudaFuncAttributeMaxDynamicSharedMemorySize, GEMM_SMEM);
    cudaFuncSetAttribute(proj_kernel,
                         cudaFuncAttributeMaxDynamicSharedMemorySize, GEMM_SMEM);

    // pre-round inputs to tf32 (RNA)
    {
        float* xr = nullptr; cudaGetSymbolAddress((void**)&xr, g_xr);
        float* wq = nullptr; cudaGetSymbolAddress((void**)&wq, g_wqkv);
        float* wp = nullptr; cudaGetSymbolAddress((void**)&wp, g_wproj);
        int n4x = M_ * C_ / 4, n4q = NC3_ * C_ / 4, n4p = C_ * C_ / 4;
        round_kernel<<<(n4x + 255) / 256, 256>>>(x, xr, n4x);
        round_kernel<<<(n4q + 255) / 256, 256>>>(qkv_w, wq, n4q);
        round_kernel<<<(n4p + 255) / 256, 256>>>(proj_w, wp, n4p);
    }

    relbias_kernel<<<(H_ * NREL + 255) / 256, 256>>>(table, ridx);
    qkv_kernel<<<dim3(NC3_ / TCN, M_ / 128), 256, GEMM_SMEM>>>(q_bias, v_bias);
    attn_kernel<<<B_ * H_, 256, attn_smem>>>();
    proj_kernel<<<dim3(C_ / TCN, M_ / 128), 256, GEMM_SMEM>>>(proj_b, out);
}

// round 15
// speedup vs baseline: 1.2109x; 1.2109x over previous
#include <cuda_runtime.h>
#include <cuda_bf16.h>
#include <math.h>
#include <stdint.h>

// Problem constants
#define B_   128
#define N_   197
#define C_   768
#define H_   12
#define HD_  64
#define NC3_ 2304
#define M_   (B_ * N_)     // 25216
#define NREL (38809)
#define SCALE 0.125f

// ---------------------------------------------------------------------------
// Scratch
// ---------------------------------------------------------------------------
__device__ float g_Q[B_ * H_ * N_ * HD_];
__device__ float g_K[B_ * H_ * N_ * HD_];
__device__ float g_V[B_ * H_ * N_ * HD_];
__device__ float g_O[M_ * C_];              // tf32-rounded by attn epilogue
__device__ float g_RB[H_ * NREL];
__device__ float g_xr[M_ * C_];             // tf32-rounded x
__device__ float g_wqkv[NC3_ * C_];         // tf32-rounded qkv_w
__device__ float g_wproj[C_ * C_];          // tf32-rounded proj_w

// ---------------------------------------------------------------------------
// helpers
// ---------------------------------------------------------------------------
__device__ __forceinline__ uint32_t f2tf(float x) {
    uint32_t u;
    asm("cvt.rna.tf32.f32 %0, %1;" : "=r"(u) : "f"(x));
    return u;
}
__device__ __forceinline__ void mma_tf32(float c[4], const uint32_t a[4],
                                         uint32_t b0, uint32_t b1) {
    asm volatile(
        "mma.sync.aligned.m16n8k8.row.col.f32.tf32.tf32.f32 "
        "{%0,%1,%2,%3}, {%4,%5,%6,%7}, {%8,%9}, {%0,%1,%2,%3};"
        : "+f"(c[0]), "+f"(c[1]), "+f"(c[2]), "+f"(c[3])
        : "r"(a[0]), "r"(a[1]), "r"(a[2]), "r"(a[3]), "r"(b0), "r"(b1));
}
__device__ __forceinline__ uint32_t smem_u32(const void* p) {
    return (uint32_t)__cvta_generic_to_shared(p);
}
__device__ __forceinline__ void cpasync16(uint32_t dst, const void* src) {
    asm volatile("cp.async.cg.shared.global [%0], [%1], 16;" :: "r"(dst), "l"(src));
}
__device__ __forceinline__ void cp_commit() {
    asm volatile("cp.async.commit_group;");
}
template <int Nn> __device__ __forceinline__ void cp_wait() {
    asm volatile("cp.async.wait_group %0;" :: "n"(Nn));
}
__device__ __forceinline__ void ldsm4(uint32_t& r0, uint32_t& r1,
                                      uint32_t& r2, uint32_t& r3, uint32_t a) {
    asm volatile("ldmatrix.sync.aligned.m8n8.x4.shared.b16 {%0,%1,%2,%3}, [%4];"
                 : "=r"(r0), "=r"(r1), "=r"(r2), "=r"(r3) : "r"(a));
}
__device__ __forceinline__ void ldsm2(uint32_t& r0, uint32_t& r1, uint32_t a) {
    asm volatile("ldmatrix.sync.aligned.m8n8.x2.shared.b16 {%0,%1}, [%2];"
                 : "=r"(r0), "=r"(r1) : "r"(a));
}

// FMA-pipe exp: exp(x) = 2^(x*log2e), x clamped >= -80 upstream.
__device__ __forceinline__ float fexp(float x) {
    float y = x * 1.44269504f;
    float r = rintf(y);
    float f = y - r;
    float p = 1.33336e-3f;
    p = fmaf(p, f, 9.61813e-3f);
    p = fmaf(p, f, 5.55041e-2f);
    p = fmaf(p, f, 2.40226507e-1f);
    p = fmaf(p, f, 6.93147182e-1f);
    p = fmaf(p, f, 1.0f);
    int i = (int)r;
    return p * __int_as_float((127 + i) << 23);
}

// ---------------------------------------------------------------------------
// tf32 pre-round (RNA) kernel
// ---------------------------------------------------------------------------
__global__ void round_kernel(const float* __restrict__ s, float* __restrict__ d, int n4) {
    int i = blockIdx.x * 256 + threadIdx.x;
    if (i < n4) {
        float4 v = ((const float4*)s)[i];
        v.x = __uint_as_float(f2tf(v.x));
        v.y = __uint_as_float(f2tf(v.y));
        v.z = __uint_as_float(f2tf(v.z));
        v.w = __uint_as_float(f2tf(v.w));
        ((float4*)d)[i] = v;
    }
}

// ---------------------------------------------------------------------------
// relbias gather
// ---------------------------------------------------------------------------
__global__ void relbias_kernel(const float* __restrict__ table,
                               const int* __restrict__ idx) {
    int i = blockIdx.x * 256 + threadIdx.x;
    if (i < H_ * NREL) {
        int h = i / NREL;
        int r = i - h * NREL;
        g_RB[i] = table[idx[r] * H_ + h];
    }
}

// ---------------------------------------------------------------------------
// Pipelined TF32 GEMM core (R6 config): 128x128 tile of A(MxK) * W(NxK)^T.
// BK=32, 3-stage cp.async, xor swizzle, ldmatrix, warp tile 32x64, 2 CTAs/SM.
// ---------------------------------------------------------------------------
#define NSTG 3
#define OPW_BYTES 16384
#define STG_BYTES 32768
#define GEMM_SMEM (NSTG * STG_BYTES)

__device__ __forceinline__ void tf32_core_pipe(
    const float* __restrict__ A, const float* __restrict__ W,
    int K, float acc[2][8][4])
{
    extern __shared__ uint32_t smp[];
    const uint32_t base = smem_u32(smp);

    const int tid = threadIdx.x;
    const int lane = tid & 31;
    const int warp = tid >> 5;
    const int wm = warp & 3, wn = warp >> 2;
    const int brow = blockIdx.y * 128;
    const int bcol = blockIdx.x * 128;

    const int r = tid >> 1;
    const int sh = (tid & 1) * 4;
    const float* Ag = A + (size_t)(brow + r) * K + sh * 4;
    const float* Wg = W + (size_t)(bcol + r) * K + sh * 4;
    uint32_t dA[4], dW[4];
    #pragma unroll
    for (int j = 0; j < 4; ++j) {
        int col = (sh + j) ^ (r & 7);
        dA[j] = base + r * 128 + col * 16;
        dW[j] = base + OPW_BYTES + r * 128 + col * 16;
    }

    const int nT = K / 32;

    auto issue = [&](int t) {
        uint32_t so = (uint32_t)(t % NSTG) * STG_BYTES;
        const float* ga = Ag + t * 32;
        const float* gw = Wg + t * 32;
        #pragma unroll
        for (int j = 0; j < 4; ++j) cpasync16(dA[j] + so, ga + j * 4);
        #pragma unroll
        for (int j = 0; j < 4; ++j) cpasync16(dW[j] + so, gw + j * 4);
        cp_commit();
    };

    issue(0);
    issue(1);

    const int ti = lane >> 3, rsub = lane & 7;
    uint32_t aB[2]; int rwA[2];
    #pragma unroll
    for (int mi = 0; mi < 2; ++mi) {
        int rr = wm * 32 + mi * 16 + ((ti & 1) << 3) + rsub;
        rwA[mi] = rr & 7;
        aB[mi] = base + rr * 128;
    }
    const int kgbA = ti >> 1;
    uint32_t bB[4]; int rwB[4];
    #pragma unroll
    for (int p = 0; p < 4; ++p) {
        int rr = wn * 64 + p * 16 + ((ti >> 1) << 3) + rsub;
        rwB[p] = rr & 7;
        bB[p] = base + OPW_BYTES + rr * 128;
    }
    const int kgbB = ti & 1;

    for (int t = 0; t < nT; ++t) {
        if (t + 1 < nT) cp_wait<1>(); else cp_wait<0>();
        __syncthreads();
        if (t + 2 < nT) issue(t + 2);
        const uint32_t so = (uint32_t)(t % NSTG) * STG_BYTES;
        #pragma unroll
        for (int kk = 0; kk < 4; ++kk) {
            uint32_t af[2][4];
            #pragma unroll
            for (int mi = 0; mi < 2; ++mi) {
                uint32_t addr = aB[mi] + so +
                    (uint32_t)((((2 * kk + kgbA) ^ rwA[mi]) & 7) << 4);
                ldsm4(af[mi][0], af[mi][1], af[mi][2], af[mi][3], addr);
            }
            #pragma unroll
            for (int p = 0; p < 4; ++p) {
                uint32_t b0a, b1a, b0b, b1b;
                uint32_t addr = bB[p] + so +
                    (uint32_t)((((2 * kk + kgbB) ^ rwB[p]) & 7) << 4);
                ldsm4(b0a, b1a, b0b, b1b, addr);
                mma_tf32(acc[0][2 * p],     af[0], b0a, b1a);
                mma_tf32(acc[1][2 * p],     af[1], b0a, b1a);
                mma_tf32(acc[0][2 * p + 1], af[0], b0b, b1b);
                mma_tf32(acc[1][2 * p + 1], af[1], b0b, b1b);
            }
        }
    }
}

// ---------------------------------------------------------------------------
// QKV GEMM + scatter epilogue
// ---------------------------------------------------------------------------
__global__ __launch_bounds__(256, 2)
void qkv_kernel(const float* __restrict__ q_bias, const float* __restrict__ v_bias)
{
    float acc[2][8][4];
    #pragma unroll
    for (int i = 0; i < 2; ++i)
        #pragma unroll
        for (int j = 0; j < 8; ++j)
            #pragma unroll
            for (int k = 0; k < 4; ++k) acc[i][j][k] = 0.f;

    tf32_core_pipe(g_xr, g_wqkv, C_, acc);

    const int lane = threadIdx.x & 31;
    const int warp = threadIdx.x >> 5;
    const int wm = warp & 3, wn = warp >> 2;
    const int brow = blockIdx.y * 128;
    const int bcol = blockIdx.x * 128;

    const int which = bcol / C_;
    const int ccbase = bcol - which * C_;

    #pragma unroll
    for (int mi = 0; mi < 2; ++mi) {
        #pragma unroll
        for (int rh = 0; rh < 2; ++rh) {
            int row = brow + wm * 32 + mi * 16 + (lane >> 2) + rh * 8;
            int b = row / N_;
            int n = row - b * N_;
            #pragma unroll
            for (int ni = 0; ni < 8; ++ni) {
                #pragma unroll
                for (int cj = 0; cj < 2; ++cj) {
                    int cc = ccbase + wn * 64 + ni * 8 + (lane & 3) * 2 + cj;
                    int h = cc >> 6;
                    int d = cc & 63;
                    size_t dst = (((size_t)(b * H_ + h) * N_) + n) * HD_ + d;
                    float v = acc[mi][ni][rh * 2 + cj];
                    if (which == 0)      g_Q[dst] = (v + q_bias[cc]) * SCALE;
                    else if (which == 1) g_K[dst] = v;
                    else                 g_V[dst] = v + v_bias[cc];
                }
            }
        }
    }
}

// ---------------------------------------------------------------------------
// Proj GEMM + bias epilogue
// ---------------------------------------------------------------------------
__global__ __launch_bounds__(256, 2)
void proj_kernel(const float* __restrict__ proj_b, float* __restrict__ out)
{
    float acc[2][8][4];
    #pragma unroll
    for (int i = 0; i < 2; ++i)
        #pragma unroll
        for (int j = 0; j < 8; ++j)
            #pragma unroll
            for (int k = 0; k < 4; ++k) acc[i][j][k] = 0.f;

    tf32_core_pipe(g_O, g_wproj, C_, acc);

    const int lane = threadIdx.x & 31;
    const int warp = threadIdx.x >> 5;
    const int wm = warp & 3, wn = warp >> 2;
    const int brow = blockIdx.y * 128;
    const int bcol = blockIdx.x * 128;

    #pragma unroll
    for (int mi = 0; mi < 2; ++mi) {
        #pragma unroll
        for (int rh = 0; rh < 2; ++rh) {
            int row = brow + wm * 32 + mi * 16 + (lane >> 2) + rh * 8;
            #pragma unroll
            for (int ni = 0; ni < 8; ++ni) {
                #pragma unroll
                for (int cj = 0; cj < 2; ++cj) {
                    int col = bcol + wn * 64 + ni * 8 + (lane & 3) * 2 + cj;
                    out[(size_t)row * C_ + col] = acc[mi][ni][rh * 2 + cj] + proj_b[col];
                }
            }
        }
    }
}

// ---------------------------------------------------------------------------
// Tensor-core fused attention (ldmatrix + mma.sync; FMA-pipe exp)
// ---------------------------------------------------------------------------
#define AP 68
#define SP 212
#define ATTN_SMEM_WORDS (208 * AP + 64 * SP + 64 * SP + 64 * AP)

__global__ __launch_bounds__(256)
void attn_kernel()
{
    extern __shared__ uint32_t smu[];
    uint32_t* Ks = smu;
    uint32_t* Vt = Ks + 208 * AP;
    float*    S  = (float*)(Vt + 64 * SP);
    uint32_t* Qs = (uint32_t*)S + 64 * SP;

    const uint32_t KsB = smem_u32(Ks);
    const uint32_t VtB = smem_u32(Vt);
    const uint32_t SB  = smem_u32(S);
    const uint32_t QsB = smem_u32(Qs);

    const int bh = blockIdx.x;
    const int h = bh % H_;
    const int b = bh / H_;
    const int tid = threadIdx.x;
    const int lane = tid & 31;
    const int warp = tid >> 5;
    const int wm = warp & 3;
    const int wn = warp >> 2;

    const float* Kg = g_K + (size_t)bh * N_ * HD_;
    const float* Vg = g_V + (size_t)bh * N_ * HD_;

    for (int i = tid; i < N_ * HD_; i += 256) {
        int m = i >> 6, d = i & 63;
        Ks[m * AP + d] = f2tf(Kg[i]);
        Vt[d * SP + m] = f2tf(Vg[i]);
    }
    for (int i = tid; i < (208 - N_) * HD_; i += 256) {
        int m = N_ + (i >> 6), d = i & 63;
        Ks[m * AP + d] = 0;
    }
    for (int i = tid; i < HD_ * (SP - N_); i += 256) {
        int d = i / (SP - N_), m = N_ + i % (SP - N_);
        Vt[d * SP + m] = 0;
    }
    __syncthreads();

    const float* rb = g_RB + (size_t)h * NREL;
    const int r0 = wm * 16 + (lane >> 2);
    const int ti = lane >> 3, rsub = lane & 7;

    const uint32_t qA = QsB + (uint32_t)((wm * 16 + ((ti & 1) << 3) + rsub) * AP) * 4
                            + (uint32_t)(ti >> 1) * 16;
    uint32_t kB[6];
    #pragma unroll
    for (int q = 0; q < 6; ++q)
        kB[q] = KsB + (uint32_t)(((4 * q + 2 * (ti >> 1) + wn) * 8 + rsub) * AP) * 4
                    + (uint32_t)(ti & 1) * 16;
    const uint32_t kB12 = KsB + (uint32_t)(((24 + wn) * 8 + (lane & 7)) * AP) * 4
                              + (uint32_t)((lane >> 3) & 1) * 16;
    const uint32_t sA = SB + (uint32_t)((wm * 16 + ((ti & 1) << 3) + rsub) * SP) * 4
                           + (uint32_t)(ti >> 1) * 16;
    uint32_t vB[2];
    #pragma unroll
    for (int q = 0; q < 2; ++q)
        vB[q] = VtB + (uint32_t)((wn * 32 + q * 16 + ((ti >> 1) << 3) + rsub) * SP) * 4
                    + (uint32_t)(ti & 1) * 16;

    for (int qb = 0; qb < 4; ++qb) {
        {
            int r = tid >> 2;
            int c0 = (tid & 3) * 16;
            int qg = qb * 64 + r;
            uint32_t* dst = &Qs[r * AP + c0];
            if (qg < N_) {
                const float* qp = g_Q + ((size_t)bh * N_ + qg) * HD_ + c0;
                #pragma unroll
                for (int j = 0; j < 16; j += 4) {
                    float4 v = *(const float4*)(qp + j);
                    dst[j]     = f2tf(v.x);
                    dst[j + 1] = f2tf(v.y);
                    dst[j + 2] = f2tf(v.z);
                    dst[j + 3] = f2tf(v.w);
                }
            } else {
                #pragma unroll
                for (int j = 0; j < 16; ++j) dst[j] = 0;
            }
        }
        __syncthreads();

        {
            float acc[13][4];
            #pragma unroll
            for (int t = 0; t < 13; ++t)
                #pragma unroll
                for (int k = 0; k < 4; ++k) acc[t][k] = 0.f;

            #pragma unroll
            for (int kk = 0; kk < 8; ++kk) {
                uint32_t af[4];
                ldsm4(af[0], af[1], af[2], af[3], qA + kk * 32);
                #pragma unroll
                for (int q = 0; q < 6; ++q) {
                    uint32_t b0a, b1a, b0b, b1b;
                    ldsm4(b0a, b1a, b0b, b1b, kB[q] + kk * 32);
                    mma_tf32(acc[2 * q],     af, b0a, b1a);
                    mma_tf32(acc[2 * q + 1], af, b0b, b1b);
                }
                uint32_t c0, c1;
                ldsm2(c0, c1, kB12 + kk * 32);
                mma_tf32(acc[12], af, c0, c1);
            }
            #pragma unroll
            for (int t = 0; t < 13; ++t) {
                int n0 = (t * 2 + wn) * 8 + (lane & 3) * 2;
                S[(r0)     * SP + n0]     = acc[t][0];
                S[(r0)     * SP + n0 + 1] = acc[t][1];
                S[(r0 + 8) * SP + n0]     = acc[t][2];
                S[(r0 + 8) * SP + n0 + 1] = acc[t][3];
            }
        }
        __syncthreads();

        for (int ri = 0; ri < 8; ++ri) {
            int r = warp * 8 + ri;
            int qg = qb * 64 + r;
            if (lane < SP - N_) S[r * SP + N_ + lane] = 0.0f;
            if (qg >= N_) continue;
            const float* rbr = rb + (size_t)qg * N_;
            float s[7];
            float mx = -3.4e38f;
            #pragma unroll
            for (int j = 0; j < 7; ++j) {
                int m = lane + 32 * j;
                s[j] = (m < N_) ? S[r * SP + m] + rbr[m] : -3.4e38f;
                mx = fmaxf(mx, s[j]);
            }
            #pragma unroll
            for (int o = 16; o > 0; o >>= 1)
                mx = fmaxf(mx, __shfl_xor_sync(0xffffffffu, mx, o));
            float sum = 0.f;
            #pragma unroll
            for (int j = 0; j < 7; ++j) {
                s[j] = fexp(fmaxf(s[j] - mx, -80.f));
                sum += s[j];
            }
            #pragma unroll
            for (int o = 16; o > 0; o >>= 1)
                sum += __shfl_xor_sync(0xffffffffu, sum, o);
            float inv = 1.0f / sum;
            uint32_t* Su = (uint32_t*)S;
            #pragma unroll
            for (int j = 0; j < 7; ++j) {
                int m = lane + 32 * j;
                if (m < N_) Su[r * SP + m] = f2tf(s[j] * inv);
            }
        }
        __syncthreads();

        {
            float acc2[4][4];
            #pragma unroll
            for (int t = 0; t < 4; ++t)
                #pragma unroll
                for (int k = 0; k < 4; ++k) acc2[t][k] = 0.f;

            #pragma unroll 2
            for (int kk = 0; kk < 26; ++kk) {
                uint32_t af[4];
                ldsm4(af[0], af[1], af[2], af[3], sA + kk * 32);
                #pragma unroll
                for (int q = 0; q < 2; ++q) {
                    uint32_t b0a, b1a, b0b, b1b;
                    ldsm4(b0a, b1a, b0b, b1b, vB[q] + kk * 32);
                    mma_tf32(acc2[2 * q],     af, b0a, b1a);
                    mma_tf32(acc2[2 * q + 1], af, b0b, b1b);
                }
            }
            #pragma unroll
            for (int rr = 0; rr < 2; ++rr) {
                int qg = qb * 64 + r0 + rr * 8;
                if (qg < N_) {
                    float* op = g_O + ((size_t)(b * N_ + qg)) * C_ + h * HD_ + wn * 32;
                    #pragma unroll
                    for (int t = 0; t < 4; ++t) {
                        op[t * 8 + (lane & 3) * 2] =
                            __uint_as_float(f2tf(acc2[t][rr * 2]));
                        op[t * 8 + (lane & 3) * 2 + 1] =
                            __uint_as_float(f2tf(acc2[t][rr * 2 + 1]));
                    }
                }
            }
        }
        __syncthreads();
    }
}

// ---------------------------------------------------------------------------
// Launch
// ---------------------------------------------------------------------------
extern "C" void kernel_launch(void* const* d_in, const int* in_sizes, int n_in,
                              void* d_out, int out_size)
{
    (void)in_sizes; (void)n_in; (void)out_size;
    const float* x      = (const float*)d_in[0];
    const float* qkv_w  = (const float*)d_in[1];
    const float* q_bias = (const float*)d_in[2];
    const float* v_bias = (const float*)d_in[3];
    const float* table  = (const float*)d_in[4];
    const float* proj_w = (const float*)d_in[5];
    const float* proj_b = (const float*)d_in[6];
    const int*   ridx   = (const int*)d_in[7];
    float* out = (float*)d_out;

    const int attn_smem = ATTN_SMEM_WORDS * (int)sizeof(uint32_t);
    cudaFuncSetAttribute(attn_kernel,
                         cudaFuncAttributeMaxDynamicSharedMemorySize, attn_smem);
    cudaFuncSetAttribute(qkv_kernel,
                         cudaFuncAttributeMaxDynamicSharedMemorySize, GEMM_SMEM);
    cudaFuncSetAttribute(proj_kernel,
                         cudaFuncAttributeMaxDynamicSharedMemorySize, GEMM_SMEM);

    // pre-round inputs to tf32 (RNA)
    {
        float* xr = nullptr; cudaGetSymbolAddress((void**)&xr, g_xr);
        float* wq = nullptr; cudaGetSymbolAddress((void**)&wq, g_wqkv);
        float* wp = nullptr; cudaGetSymbolAddress((void**)&wp, g_wproj);
        int n4x = M_ * C_ / 4, n4q = NC3_ * C_ / 4, n4p = C_ * C_ / 4;
        round_kernel<<<(n4x + 255) / 256, 256>>>(x, xr, n4x);
        round_kernel<<<(n4q + 255) / 256, 256>>>(qkv_w, wq, n4q);
        round_kernel<<<(n4p + 255) / 256, 256>>>(proj_w, wp, n4p);
    }

    relbias_kernel<<<(H_ * NREL + 255) / 256, 256>>>(table, ridx);
    qkv_kernel<<<dim3(NC3_ / 128, M_ / 128), 256, GEMM_SMEM>>>(q_bias, v_bias);
    attn_kernel<<<B_ * H_, 256, attn_smem>>>();
    proj_kernel<<<dim3(C_ / 128, M_ / 128), 256, GEMM_SMEM>>>(proj_b, out);
}

// round 16
// speedup vs baseline: 1.3276x; 1.0963x over previous
#include <cuda_runtime.h>
#include <cuda_bf16.h>
#include <math.h>
#include <stdint.h>

// Problem constants
#define B_   128
#define N_   197
#define C_   768
#define H_   12
#define HD_  64
#define NC3_ 2304
#define M_   (B_ * N_)     // 25216
#define NREL (38809)
#define SCALE 0.125f

// ---------------------------------------------------------------------------
// Scratch
// ---------------------------------------------------------------------------
__device__ float g_Q[B_ * H_ * N_ * HD_];
__device__ float g_K[B_ * H_ * N_ * HD_];
__device__ float g_V[B_ * H_ * N_ * HD_];
__device__ float g_O[M_ * C_];              // tf32-rounded by attn epilogue
__device__ float g_RB[H_ * NREL];
__device__ float g_xr[M_ * C_];             // tf32-rounded x
__device__ float g_wqkv[NC3_ * C_];         // tf32-rounded qkv_w
__device__ float g_wproj[C_ * C_];          // tf32-rounded proj_w

// ---------------------------------------------------------------------------
// helpers
// ---------------------------------------------------------------------------
__device__ __forceinline__ uint32_t f2tf(float x) {
    uint32_t u;
    asm("cvt.rna.tf32.f32 %0, %1;" : "=r"(u) : "f"(x));
    return u;
}
__device__ __forceinline__ void mma_tf32(float c[4], const uint32_t a[4],
                                         uint32_t b0, uint32_t b1) {
    asm volatile(
        "mma.sync.aligned.m16n8k8.row.col.f32.tf32.tf32.f32 "
        "{%0,%1,%2,%3}, {%4,%5,%6,%7}, {%8,%9}, {%0,%1,%2,%3};"
        : "+f"(c[0]), "+f"(c[1]), "+f"(c[2]), "+f"(c[3])
        : "r"(a[0]), "r"(a[1]), "r"(a[2]), "r"(a[3]), "r"(b0), "r"(b1));
}
__device__ __forceinline__ uint32_t smem_u32(const void* p) {
    return (uint32_t)__cvta_generic_to_shared(p);
}
__device__ __forceinline__ void cpasync16(uint32_t dst, const void* src) {
    asm volatile("cp.async.cg.shared.global [%0], [%1], 16;" :: "r"(dst), "l"(src));
}
__device__ __forceinline__ void cp_commit() {
    asm volatile("cp.async.commit_group;");
}
template <int Nn> __device__ __forceinline__ void cp_wait() {
    asm volatile("cp.async.wait_group %0;" :: "n"(Nn));
}
__device__ __forceinline__ void ldsm4(uint32_t& r0, uint32_t& r1,
                                      uint32_t& r2, uint32_t& r3, uint32_t a) {
    asm volatile("ldmatrix.sync.aligned.m8n8.x4.shared.b16 {%0,%1,%2,%3}, [%4];"
                 : "=r"(r0), "=r"(r1), "=r"(r2), "=r"(r3) : "r"(a));
}

// ---------------------------------------------------------------------------
// tf32 pre-round (RNA) kernel
// ---------------------------------------------------------------------------
__global__ void round_kernel(const float* __restrict__ s, float* __restrict__ d, int n4) {
    int i = blockIdx.x * 256 + threadIdx.x;
    if (i < n4) {
        float4 v = ((const float4*)s)[i];
        v.x = __uint_as_float(f2tf(v.x));
        v.y = __uint_as_float(f2tf(v.y));
        v.z = __uint_as_float(f2tf(v.z));
        v.w = __uint_as_float(f2tf(v.w));
        ((float4*)d)[i] = v;
    }
}

// ---------------------------------------------------------------------------
// relbias gather
// ---------------------------------------------------------------------------
__global__ void relbias_kernel(const float* __restrict__ table,
                               const int* __restrict__ idx) {
    int i = blockIdx.x * 256 + threadIdx.x;
    if (i < H_ * NREL) {
        int h = i / NREL;
        int r = i - h * NREL;
        g_RB[i] = table[idx[r] * H_ + h];
    }
}

// ---------------------------------------------------------------------------
// Pipelined TF32 GEMM core (R6 config, unchanged): 128x128 tile.
// ---------------------------------------------------------------------------
#define NSTG 3
#define OPW_BYTES 16384
#define STG_BYTES 32768
#define GEMM_SMEM (NSTG * STG_BYTES)

__device__ __forceinline__ void tf32_core_pipe(
    const float* __restrict__ A, const float* __restrict__ W,
    int K, float acc[2][8][4])
{
    extern __shared__ uint32_t smp[];
    const uint32_t base = smem_u32(smp);

    const int tid = threadIdx.x;
    const int lane = tid & 31;
    const int warp = tid >> 5;
    const int wm = warp & 3, wn = warp >> 2;
    const int brow = blockIdx.y * 128;
    const int bcol = blockIdx.x * 128;

    const int r = tid >> 1;
    const int sh = (tid & 1) * 4;
    const float* Ag = A + (size_t)(brow + r) * K + sh * 4;
    const float* Wg = W + (size_t)(bcol + r) * K + sh * 4;
    uint32_t dA[4], dW[4];
    #pragma unroll
    for (int j = 0; j < 4; ++j) {
        int col = (sh + j) ^ (r & 7);
        dA[j] = base + r * 128 + col * 16;
        dW[j] = base + OPW_BYTES + r * 128 + col * 16;
    }

    const int nT = K / 32;

    auto issue = [&](int t) {
        uint32_t so = (uint32_t)(t % NSTG) * STG_BYTES;
        const float* ga = Ag + t * 32;
        const float* gw = Wg + t * 32;
        #pragma unroll
        for (int j = 0; j < 4; ++j) cpasync16(dA[j] + so, ga + j * 4);
        #pragma unroll
        for (int j = 0; j < 4; ++j) cpasync16(dW[j] + so, gw + j * 4);
        cp_commit();
    };

    issue(0);
    issue(1);

    const int ti = lane >> 3, rsub = lane & 7;
    uint32_t aB[2]; int rwA[2];
    #pragma unroll
    for (int mi = 0; mi < 2; ++mi) {
        int rr = wm * 32 + mi * 16 + ((ti & 1) << 3) + rsub;
        rwA[mi] = rr & 7;
        aB[mi] = base + rr * 128;
    }
    const int kgbA = ti >> 1;
    uint32_t bB[4]; int rwB[4];
    #pragma unroll
    for (int p = 0; p < 4; ++p) {
        int rr = wn * 64 + p * 16 + ((ti >> 1) << 3) + rsub;
        rwB[p] = rr & 7;
        bB[p] = base + OPW_BYTES + rr * 128;
    }
    const int kgbB = ti & 1;

    for (int t = 0; t < nT; ++t) {
        if (t + 1 < nT) cp_wait<1>(); else cp_wait<0>();
        __syncthreads();
        if (t + 2 < nT) issue(t + 2);
        const uint32_t so = (uint32_t)(t % NSTG) * STG_BYTES;
        #pragma unroll
        for (int kk = 0; kk < 4; ++kk) {
            uint32_t af[2][4];
            #pragma unroll
            for (int mi = 0; mi < 2; ++mi) {
                uint32_t addr = aB[mi] + so +
                    (uint32_t)((((2 * kk + kgbA) ^ rwA[mi]) & 7) << 4);
                ldsm4(af[mi][0], af[mi][1], af[mi][2], af[mi][3], addr);
            }
            #pragma unroll
            for (int p = 0; p < 4; ++p) {
                uint32_t b0a, b1a, b0b, b1b;
                uint32_t addr = bB[p] + so +
                    (uint32_t)((((2 * kk + kgbB) ^ rwB[p]) & 7) << 4);
                ldsm4(b0a, b1a, b0b, b1b, addr);
                mma_tf32(acc[0][2 * p],     af[0], b0a, b1a);
                mma_tf32(acc[1][2 * p],     af[1], b0a, b1a);
                mma_tf32(acc[0][2 * p + 1], af[0], b0b, b1b);
                mma_tf32(acc[1][2 * p + 1], af[1], b0b, b1b);
            }
        }
    }
}

// ---------------------------------------------------------------------------
// QKV GEMM + scatter epilogue
// ---------------------------------------------------------------------------
__global__ __launch_bounds__(256, 2)
void qkv_kernel(const float* __restrict__ q_bias, const float* __restrict__ v_bias)
{
    float acc[2][8][4];
    #pragma unroll
    for (int i = 0; i < 2; ++i)
        #pragma unroll
        for (int j = 0; j < 8; ++j)
            #pragma unroll
            for (int k = 0; k < 4; ++k) acc[i][j][k] = 0.f;

    tf32_core_pipe(g_xr, g_wqkv, C_, acc);

    const int lane = threadIdx.x & 31;
    const int warp = threadIdx.x >> 5;
    const int wm = warp & 3, wn = warp >> 2;
    const int brow = blockIdx.y * 128;
    const int bcol = blockIdx.x * 128;

    const int which = bcol / C_;
    const int ccbase = bcol - which * C_;

    #pragma unroll
    for (int mi = 0; mi < 2; ++mi) {
        #pragma unroll
        for (int rh = 0; rh < 2; ++rh) {
            int row = brow + wm * 32 + mi * 16 + (lane >> 2) + rh * 8;
            int b = row / N_;
            int n = row - b * N_;
            #pragma unroll
            for (int ni = 0; ni < 8; ++ni) {
                #pragma unroll
                for (int cj = 0; cj < 2; ++cj) {
                    int cc = ccbase + wn * 64 + ni * 8 + (lane & 3) * 2 + cj;
                    int h = cc >> 6;
                    int d = cc & 63;
                    size_t dst = (((size_t)(b * H_ + h) * N_) + n) * HD_ + d;
                    float v = acc[mi][ni][rh * 2 + cj];
                    if (which == 0)      g_Q[dst] = (v + q_bias[cc]) * SCALE;
                    else if (which == 1) g_K[dst] = v;
                    else                 g_V[dst] = v + v_bias[cc];
                }
            }
        }
    }
}

// ---------------------------------------------------------------------------
// Proj GEMM + bias epilogue
// ---------------------------------------------------------------------------
__global__ __launch_bounds__(256, 2)
void proj_kernel(const float* __restrict__ proj_b, float* __restrict__ out)
{
    float acc[2][8][4];
    #pragma unroll
    for (int i = 0; i < 2; ++i)
        #pragma unroll
        for (int j = 0; j < 8; ++j)
            #pragma unroll
            for (int k = 0; k < 4; ++k) acc[i][j][k] = 0.f;

    tf32_core_pipe(g_O, g_wproj, C_, acc);

    const int lane = threadIdx.x & 31;
    const int warp = threadIdx.x >> 5;
    const int wm = warp & 3, wn = warp >> 2;
    const int brow = blockIdx.y * 128;
    const int bcol = blockIdx.x * 128;

    #pragma unroll
    for (int mi = 0; mi < 2; ++mi) {
        #pragma unroll
        for (int rh = 0; rh < 2; ++rh) {
            int row = brow + wm * 32 + mi * 16 + (lane >> 2) + rh * 8;
            #pragma unroll
            for (int ni = 0; ni < 8; ++ni) {
                #pragma unroll
                for (int cj = 0; cj < 2; ++cj) {
                    int col = bcol + wn * 64 + ni * 8 + (lane & 3) * 2 + cj;
                    out[(size_t)row * C_ + col] = acc[mi][ni][rh * 2 + cj] + proj_b[col];
                }
            }
        }
    }
}

// ---------------------------------------------------------------------------
// Tensor-core fused attention — 512 threads (16 warps).
// Warp layout: wm = warp&3 (16-row band of the 64-row q-block),
//              wn = warp>>2 (quarter of the N / d dimension).
// QK^T: 26 8-col tiles as 13 16-col pairs split {4,3,3,3} across wn.
// Softmax: 4 rows per warp. PV: 16 d-cols per warp.
// ---------------------------------------------------------------------------
#define AP 68
#define SP 212
#define ATTN_SMEM_WORDS (208 * AP + 64 * SP + 64 * SP + 64 * AP)

__global__ __launch_bounds__(512)
void attn_kernel()
{
    extern __shared__ uint32_t smu[];
    uint32_t* Ks = smu;                      // [208][AP] tf32
    uint32_t* Vt = Ks + 208 * AP;            // [64][SP]  tf32 (V transposed)
    float*    S  = (float*)(Vt + 64 * SP);   // [64][SP]  scores / probs
    uint32_t* Qs = (uint32_t*)S + 64 * SP;   // [64][AP]  tf32

    const uint32_t KsB = smem_u32(Ks);
    const uint32_t VtB = smem_u32(Vt);
    const uint32_t SB  = smem_u32(S);
    const uint32_t QsB = smem_u32(Qs);

    const int bh = blockIdx.x;
    const int h = bh % H_;
    const int b = bh / H_;
    const int tid = threadIdx.x;
    const int lane = tid & 31;
    const int warp = tid >> 5;       // 0..15
    const int wm = warp & 3;
    const int wn = warp >> 2;        // 0..3

    const float* Kg = g_K + (size_t)bh * N_ * HD_;
    const float* Vg = g_V + (size_t)bh * N_ * HD_;

    for (int i = tid; i < N_ * HD_; i += 512) {
        int m = i >> 6, d = i & 63;
        Ks[m * AP + d] = f2tf(Kg[i]);
        Vt[d * SP + m] = f2tf(Vg[i]);
    }
    for (int i = tid; i < (208 - N_) * HD_; i += 512) {
        int m = N_ + (i >> 6), d = i & 63;
        Ks[m * AP + d] = 0;
    }
    for (int i = tid; i < HD_ * (SP - N_); i += 512) {
        int d = i / (SP - N_), m = N_ + i % (SP - N_);
        Vt[d * SP + m] = 0;
    }
    __syncthreads();

    const float* rb = g_RB + (size_t)h * NREL;
    const int r0 = wm * 16 + (lane >> 2);
    const int ti = lane >> 3, rsub = lane & 7;

    // A-fragment base (16 rows of Q / S per wm band)
    const uint32_t qA = QsB + (uint32_t)((wm * 16 + ((ti & 1) << 3) + rsub) * AP) * 4
                            + (uint32_t)(ti >> 1) * 16;
    const uint32_t sA = SB + (uint32_t)((wm * 16 + ((ti & 1) << 3) + rsub) * SP) * 4
                           + (uint32_t)(ti >> 1) * 16;

    // QK^T pair-tile split across wn: counts {4,3,3,3}, bases {0,4,7,10}
    const int np = (wn == 0) ? 4 : 3;
    const int pb = (wn == 0) ? 0 : (4 + 3 * (wn - 1));
    uint32_t kB[4];
    #pragma unroll
    for (int t = 0; t < 4; ++t) {
        int R0 = (pb + t) * 16;
        kB[t] = KsB + (uint32_t)((R0 + ((ti >> 1) << 3) + rsub) * AP) * 4
                    + (uint32_t)(ti & 1) * 16;
    }
    // PV: one 16-row Vt pair per warp (d cols wn*16..wn*16+15)
    const uint32_t vB = VtB + (uint32_t)((wn * 16 + ((ti >> 1) << 3) + rsub) * SP) * 4
                            + (uint32_t)(ti & 1) * 16;

    for (int qb = 0; qb < 4; ++qb) {
        // ---- stage Q block (512 threads: 64 rows x 8-col segments) ----
        {
            int r = tid >> 3;
            int c0 = (tid & 7) * 8;
            int qg = qb * 64 + r;
            uint32_t* dst = &Qs[r * AP + c0];
            if (qg < N_) {
                const float* qp = g_Q + ((size_t)bh * N_ + qg) * HD_ + c0;
                #pragma unroll
                for (int j = 0; j < 8; j += 4) {
                    float4 v = *(const float4*)(qp + j);
                    dst[j]     = f2tf(v.x);
                    dst[j + 1] = f2tf(v.y);
                    dst[j + 2] = f2tf(v.z);
                    dst[j + 3] = f2tf(v.w);
                }
            } else {
                #pragma unroll
                for (int j = 0; j < 8; ++j) dst[j] = 0;
            }
        }
        __syncthreads();

        // ---- QK^T: np 16-col pairs per warp ----
        {
            float acc[4][2][4];
            #pragma unroll
            for (int t = 0; t < 4; ++t)
                #pragma unroll
                for (int hh = 0; hh < 2; ++hh)
                    #pragma unroll
                    for (int k = 0; k < 4; ++k) acc[t][hh][k] = 0.f;

            #pragma unroll
            for (int kk = 0; kk < 8; ++kk) {
                uint32_t af[4];
                ldsm4(af[0], af[1], af[2], af[3], qA + kk * 32);
                #pragma unroll
                for (int t = 0; t < 4; ++t) {
                    if (t < np) {
                        uint32_t b0a, b1a, b0b, b1b;
                        ldsm4(b0a, b1a, b0b, b1b, kB[t] + kk * 32);
                        mma_tf32(acc[t][0], af, b0a, b1a);
                        mma_tf32(acc[t][1], af, b0b, b1b);
                    }
                }
            }
            #pragma unroll
            for (int t = 0; t < 4; ++t) {
                if (t < np) {
                    #pragma unroll
                    for (int hh = 0; hh < 2; ++hh) {
                        int n0 = (pb + t) * 16 + hh * 8 + (lane & 3) * 2;
                        S[(r0)     * SP + n0]     = acc[t][hh][0];
                        S[(r0)     * SP + n0 + 1] = acc[t][hh][1];
                        S[(r0 + 8) * SP + n0]     = acc[t][hh][2];
                        S[(r0 + 8) * SP + n0 + 1] = acc[t][hh][3];
                    }
                }
            }
        }
        __syncthreads();

        // ---- softmax: 4 rows per warp ----
        #pragma unroll
        for (int ri = 0; ri < 4; ++ri) {
            int r = warp * 4 + ri;
            int qg = qb * 64 + r;
            if (lane < SP - N_) S[r * SP + N_ + lane] = 0.0f;
            if (qg >= N_) continue;
            const float* rbr = rb + (size_t)qg * N_;
            float s[7];
            float mx = -3.4e38f;
            #pragma unroll
            for (int j = 0; j < 7; ++j) {
                int m = lane + 32 * j;
                s[j] = (m < N_) ? S[r * SP + m] + rbr[m] : -3.4e38f;
                mx = fmaxf(mx, s[j]);
            }
            #pragma unroll
            for (int o = 16; o > 0; o >>= 1)
                mx = fmaxf(mx, __shfl_xor_sync(0xffffffffu, mx, o));
            float sum = 0.f;
            #pragma unroll
            for (int j = 0; j < 7; ++j) {
                s[j] = __expf(s[j] - mx);
                sum += s[j];
            }
            #pragma unroll
            for (int o = 16; o > 0; o >>= 1)
                sum += __shfl_xor_sync(0xffffffffu, sum, o);
            float inv = 1.0f / sum;
            uint32_t* Su = (uint32_t*)S;
            #pragma unroll
            for (int j = 0; j < 7; ++j) {
                int m = lane + 32 * j;
                if (m < N_) Su[r * SP + m] = f2tf(s[j] * inv);
            }
        }
        __syncthreads();

        // ---- PV: 16 d-cols per warp, 26 k-steps ----
        {
            float acc2[2][4];
            #pragma unroll
            for (int hh = 0; hh < 2; ++hh)
                #pragma unroll
                for (int k = 0; k < 4; ++k) acc2[hh][k] = 0.f;

            #pragma unroll 2
            for (int kk = 0; kk < 26; ++kk) {
                uint32_t af[4];
                ldsm4(af[0], af[1], af[2], af[3], sA + kk * 32);
                uint32_t b0a, b1a, b0b, b1b;
                ldsm4(b0a, b1a, b0b, b1b, vB + kk * 32);
                mma_tf32(acc2[0], af, b0a, b1a);
                mma_tf32(acc2[1], af, b0b, b1b);
            }
            #pragma unroll
            for (int rr = 0; rr < 2; ++rr) {
                int qg = qb * 64 + r0 + rr * 8;
                if (qg < N_) {
                    float* op = g_O + ((size_t)(b * N_ + qg)) * C_ + h * HD_ + wn * 16;
                    #pragma unroll
                    for (int hh = 0; hh < 2; ++hh) {
                        op[hh * 8 + (lane & 3) * 2] =
                            __uint_as_float(f2tf(acc2[hh][rr * 2]));
                        op[hh * 8 + (lane & 3) * 2 + 1] =
                            __uint_as_float(f2tf(acc2[hh][rr * 2 + 1]));
                    }
                }
            }
        }
        __syncthreads();
    }
}

// ---------------------------------------------------------------------------
// Launch
// ---------------------------------------------------------------------------
extern "C" void kernel_launch(void* const* d_in, const int* in_sizes, int n_in,
                              void* d_out, int out_size)
{
    (void)in_sizes; (void)n_in; (void)out_size;
    const float* x      = (const float*)d_in[0];
    const float* qkv_w  = (const float*)d_in[1];
    const float* q_bias = (const float*)d_in[2];
    const float* v_bias = (const float*)d_in[3];
    const float* table  = (const float*)d_in[4];
    const float* proj_w = (const float*)d_in[5];
    const float* proj_b = (const float*)d_in[6];
    const int*   ridx   = (const int*)d_in[7];
    float* out = (float*)d_out;

    const int attn_smem = ATTN_SMEM_WORDS * (int)sizeof(uint32_t);
    cudaFuncSetAttribute(attn_kernel,
                         cudaFuncAttributeMaxDynamicSharedMemorySize, attn_smem);
    cudaFuncSetAttribute(qkv_kernel,
                         cudaFuncAttributeMaxDynamicSharedMemorySize, GEMM_SMEM);
    cudaFuncSetAttribute(proj_kernel,
                         cudaFuncAttributeMaxDynamicSharedMemorySize, GEMM_SMEM);

    // pre-round inputs to tf32 (RNA)
    {
        float* xr = nullptr; cudaGetSymbolAddress((void**)&xr, g_xr);
        float* wq = nullptr; cudaGetSymbolAddress((void**)&wq, g_wqkv);
        float* wp = nullptr; cudaGetSymbolAddress((void**)&wp, g_wproj);
        int n4x = M_ * C_ / 4, n4q = NC3_ * C_ / 4, n4p = C_ * C_ / 4;
        round_kernel<<<(n4x + 255) / 256, 256>>>(x, xr, n4x);
        round_kernel<<<(n4q + 255) / 256, 256>>>(qkv_w, wq, n4q);
        round_kernel<<<(n4p + 255) / 256, 256>>>(proj_w, wp, n4p);
    }

    relbias_kernel<<<(H_ * NREL + 255) / 256, 256>>>(table, ridx);
    qkv_kernel<<<dim3(NC3_ / 128, M_ / 128), 256, GEMM_SMEM>>>(q_bias, v_bias);
    attn_kernel<<<B_ * H_, 512, attn_smem>>>();
    proj_kernel<<<dim3(C_ / 128, M_ / 128), 256, GEMM_SMEM>>>(proj_b, out);
}